// round 14
// baseline (speedup 1.0000x reference)
#include <cuda_runtime.h>
#include <cuda_fp16.h>
#include <math.h>
#include <stdint.h>

#define N_TOK 16384
#define D_DIM 1024
#define E_NUM 16
#define H_DIM 4096
#define NC_DIM 1000
#define CAP 2048
#define NB_GATE (N_TOK/8)

typedef __half fp16;

// ---------------- device scratch ----------------
__device__ __align__(16) fp16 g_disp_hi[(size_t)E_NUM*CAP*D_DIM];
__device__ __align__(16) fp16 g_disp_lo[(size_t)E_NUM*CAP*D_DIM];
__device__ __align__(16) fp16 g_h_hi[(size_t)E_NUM*CAP*H_DIM];
__device__ __align__(16) fp16 g_h_lo[(size_t)E_NUM*CAP*H_DIM];
__device__ __align__(16) fp16 g_y_hi[(size_t)N_TOK*D_DIM];
__device__ __align__(16) fp16 g_y_lo[(size_t)N_TOK*D_DIM];
__device__ __align__(16) fp16 g_w1t_hi[(size_t)E_NUM*H_DIM*D_DIM];
__device__ __align__(16) fp16 g_w1t_lo[(size_t)E_NUM*H_DIM*D_DIM];
__device__ __align__(16) fp16 g_w2t_hi[(size_t)E_NUM*D_DIM*H_DIM];
__device__ __align__(16) fp16 g_w2t_lo[(size_t)E_NUM*D_DIM*H_DIM];
__device__ __align__(16) fp16 g_wlt_hi[(size_t)1024*D_DIM];
__device__ __align__(16) fp16 g_wlt_lo[(size_t)1024*D_DIM];
__device__ __align__(16) float g_wgt[16*1024];
__device__ int   g_idx[N_TOK];
__device__ float g_gate[N_TOK];
__device__ int   g_lrank[N_TOK];
__device__ int   g_bhist[NB_GATE][E_NUM];
__device__ float g_bprob[NB_GATE][E_NUM];
__device__ int   g_boff[NB_GATE][E_NUM];
__device__ int   g_count[E_NUM];
__device__ float g_probsum[E_NUM];
__device__ int   g_inv[E_NUM*CAP];

// ---------------- PTX helpers ----------------
__device__ __forceinline__ uint32_t smem_u32(const void* p) {
    return (uint32_t)__cvta_generic_to_shared(p);
}
__device__ __forceinline__ void cpa(uint32_t dst, const void* src) {
    asm volatile("cp.async.cg.shared.global [%0], [%1], 16;" :: "r"(dst), "l"(src) : "memory");
}
__device__ __forceinline__ void cpa_commit() { asm volatile("cp.async.commit_group;" ::: "memory"); }
template<int N> __device__ __forceinline__ void cpa_wait() {
    asm volatile("cp.async.wait_group %0;" :: "n"(N) : "memory");
}
__device__ __forceinline__ void ldsm4(uint32_t* r, uint32_t a) {
    asm volatile("ldmatrix.sync.aligned.m8n8.x4.shared.b16 {%0,%1,%2,%3}, [%4];"
                 : "=r"(r[0]), "=r"(r[1]), "=r"(r[2]), "=r"(r[3]) : "r"(a));
}
// fp16 inputs, fp32 accumulate
__device__ __forceinline__ void mma_f32acc(float* d, const uint32_t* a, const uint32_t* b) {
    asm volatile(
        "mma.sync.aligned.m16n8k16.row.col.f32.f16.f16.f32 "
        "{%0,%1,%2,%3}, {%4,%5,%6,%7}, {%8,%9}, {%0,%1,%2,%3};"
        : "+f"(d[0]), "+f"(d[1]), "+f"(d[2]), "+f"(d[3])
        : "r"(a[0]), "r"(a[1]), "r"(a[2]), "r"(a[3]), "r"(b[0]), "r"(b[1]));
}
// fp16 inputs, fp16 accumulate (2 b32 regs = 4 halves)
__device__ __forceinline__ void mma_f16acc(uint32_t* d, const uint32_t* a, const uint32_t* b) {
    asm volatile(
        "mma.sync.aligned.m16n8k16.row.col.f16.f16.f16.f16 "
        "{%0,%1}, {%2,%3,%4,%5}, {%6,%7}, {%0,%1};"
        : "+r"(d[0]), "+r"(d[1])
        : "r"(a[0]), "r"(a[1]), "r"(a[2]), "r"(a[3]), "r"(b[0]), "r"(b[1]));
}

// packed fp16 2-term split: 2 floats -> half2 hi + half2 lo (as u32)
__device__ __forceinline__ void split2u(float a, float b, uint32_t& hi, uint32_t& lo) {
    half2 h = __float22half2_rn(make_float2(a, b));
    hi = *(uint32_t*)&h;
    float2 hf = __half22float2(h);
    half2 l = __float22half2_rn(make_float2(a - hf.x, b - hf.y));
    lo = *(uint32_t*)&l;
}
__device__ __forceinline__ void split2(float a, float b, fp16* hi, fp16* lo) {
    uint32_t h, l;
    split2u(a, b, h, l);
    *(uint32_t*)hi = h; *(uint32_t*)lo = l;
}

// ---------------- Wg transpose ----------------
__global__ void k_wgt(const float* __restrict__ Wg) {
    int i = blockIdx.x * 256 + threadIdx.x;
    int d = i >> 4, e = i & 15;
    g_wgt[e * 1024 + d] = Wg[i];
}

// ---------------- gating ----------------
__global__ void k_gate(const float* __restrict__ x) {
    int warp = threadIdx.x >> 5, lane = threadIdx.x & 31;
    int t = blockIdx.x * 8 + warp;
    __shared__ float s_prob[E_NUM];
    __shared__ int s_idx[8];
    if (threadIdx.x < E_NUM) s_prob[threadIdx.x] = 0.f;
    __syncthreads();
    float acc[E_NUM];
#pragma unroll
    for (int e = 0; e < E_NUM; e++) acc[e] = 0.f;
    const float4* xr = (const float4*)(x + (size_t)t * D_DIM);
    const float4* wt = (const float4*)g_wgt;
#pragma unroll
    for (int j = 0; j < 8; j++) {
        int i = lane + 32 * j;
        float4 xv = xr[i];
#pragma unroll
        for (int e = 0; e < E_NUM; e++) {
            float4 w = __ldg(wt + (size_t)e * 256 + i);
            acc[e] = fmaf(xv.x, w.x, fmaf(xv.y, w.y,
                     fmaf(xv.z, w.z, fmaf(xv.w, w.w, acc[e]))));
        }
    }
#pragma unroll
    for (int e = 0; e < E_NUM; e++)
#pragma unroll
        for (int o = 16; o > 0; o >>= 1) acc[e] += __shfl_xor_sync(0xffffffffu, acc[e], o);
    if (lane == 0) {
        float m = acc[0]; int ai = 0;
#pragma unroll
        for (int e = 1; e < E_NUM; e++) if (acc[e] > m) { m = acc[e]; ai = e; }
        float p[E_NUM]; float s = 0.f;
#pragma unroll
        for (int e = 0; e < E_NUM; e++) { p[e] = expf(acc[e] - m); s += p[e]; }
        float inv = 1.f / s;
#pragma unroll
        for (int e = 0; e < E_NUM; e++) atomicAdd(&s_prob[e], p[e] * inv);
        g_idx[t] = ai; g_gate[t] = p[ai] * inv; s_idx[warp] = ai;
    }
    __syncthreads();
    if (threadIdx.x == 0) {
        int cnt[E_NUM];
#pragma unroll
        for (int e = 0; e < E_NUM; e++) cnt[e] = 0;
#pragma unroll
        for (int w = 0; w < 8; w++) {
            int e = s_idx[w];
            g_lrank[blockIdx.x * 8 + w] = cnt[e];
            cnt[e]++;
        }
#pragma unroll
        for (int e = 0; e < E_NUM; e++) g_bhist[blockIdx.x][e] = cnt[e];
    }
    if (threadIdx.x < E_NUM) g_bprob[blockIdx.x][threadIdx.x] = s_prob[threadIdx.x];
}

// ---------------- scan + probsum + pad ----------------
__global__ void k_scan() {
    const int PB = NB_GATE / 256;
    int e = blockIdx.x, tid = threadIdx.x;
    int v[PB]; int s = 0;
    float ps = 0.f;
#pragma unroll
    for (int i = 0; i < PB; i++) {
        v[i] = g_bhist[tid * PB + i][e];
        s += v[i];
        ps += g_bprob[tid * PB + i][e];
    }
    __shared__ int sh[256];
    __shared__ float sp[256];
    sh[tid] = s; sp[tid] = ps;
    __syncthreads();
    for (int o = 1; o < 256; o <<= 1) {
        int q = (tid >= o) ? sh[tid - o] : 0;
        __syncthreads(); sh[tid] += q; __syncthreads();
    }
    int off = sh[tid] - s;
#pragma unroll
    for (int i = 0; i < PB; i++) { g_boff[tid * PB + i][e] = off; off += v[i]; }
    for (int o = 128; o > 0; o >>= 1) {
        if (tid < o) sp[tid] += sp[tid + o];
        __syncthreads();
    }
    if (tid == 0) { g_count[e] = sh[255]; g_probsum[e] = sp[0]; }
    __syncthreads();
    int c = sh[255]; if (c > CAP) c = CAP;
    int r1 = (c + 127) & ~127; if (r1 > CAP) r1 = CAP;
    for (int r = c; r < r1; r++) {
        size_t b = ((size_t)e * CAP + r) * D_DIM + tid * 4;
        *(float2*)(g_disp_hi + b) = make_float2(0.f, 0.f);
        *(float2*)(g_disp_lo + b) = make_float2(0.f, 0.f);
    }
    for (int r = c + tid; r < r1; r += 256) g_inv[e * CAP + r] = -1;
}

// wsplit body: in [E,R,C] fp32 -> out [E,Cpad,R] fp16 hi/lo
__device__ __forceinline__ void wsplit_body(
    const float* __restrict__ in, fp16* __restrict__ ohi, fp16* __restrict__ olo,
    int R, int C, int Cpad, int bx, int by, int bz, int tid)
{
    __shared__ float s[32][33];
    const float* ip = in + (size_t)bz * R * C;
    size_t ob = (size_t)bz * Cpad * R;
    int c0 = bx * 32, r0 = by * 32;
    int tx = tid & 31, ty = tid >> 5;
#pragma unroll
    for (int k = 0; k < 4; k++) {
        int r = r0 + ty + 8 * k, c = c0 + tx;
        s[ty + 8 * k][tx] = (c < C) ? ip[(size_t)r * C + c] : 0.f;
    }
    __syncthreads();
    int cl = tid >> 3, rg = (tid & 7) * 4;
    int n = c0 + cl;
    uint32_t h01, l01, h23, l23;
    split2u(s[rg + 0][cl], s[rg + 1][cl], h01, l01);
    split2u(s[rg + 2][cl], s[rg + 3][cl], h23, l23);
    size_t o = ob + (size_t)n * R + r0 + rg;
    *(uint2*)(ohi + o) = make_uint2(h01, h23);
    *(uint2*)(olo + o) = make_uint2(l01, l23);
}

__global__ void k_ws1(const float* __restrict__ W1) {
    wsplit_body(W1, g_w1t_hi, g_w1t_lo, D_DIM, H_DIM, H_DIM,
                blockIdx.x, blockIdx.y, blockIdx.z, threadIdx.x);
}
__global__ void k_ws2(const float* __restrict__ W2) {
    wsplit_body(W2, g_w2t_hi, g_w2t_lo, H_DIM, D_DIM, D_DIM,
                blockIdx.x, blockIdx.y, blockIdx.z, threadIdx.x);
}
__global__ void k_wsl(const float* __restrict__ Wl) {
    wsplit_body(Wl, g_wlt_hi, g_wlt_lo, D_DIM, NC_DIM, 1024,
                blockIdx.x, blockIdx.y, 0, threadIdx.x);
}

// dispatch
__global__ void k_dispatch(const float* __restrict__ x) {
    int t = blockIdx.x, tid = threadIdx.x;
    int e = g_idx[t];
    int pos = g_boff[t >> 3][e] + g_lrank[t];
    if (pos < CAP) {
        if (tid == 0) g_inv[e * CAP + pos] = t;
        float4 v = ((const float4*)(x + (size_t)t * D_DIM))[tid];
        size_t o = ((size_t)e * CAP + pos) * D_DIM + tid * 4;
        uint32_t h01, l01, h23, l23;
        split2u(v.x, v.y, h01, l01);
        split2u(v.z, v.w, h23, l23);
        *(uint2*)(g_disp_hi + o) = make_uint2(h01, h23);
        *(uint2*)(g_disp_lo + o) = make_uint2(l01, l23);
    } else {
        size_t o = (size_t)t * D_DIM + tid * 4;
        *(float2*)(g_y_hi + o) = make_float2(0.f, 0.f);
        *(float2*)(g_y_lo + o) = make_float2(0.f, 0.f);
    }
}

__global__ void k_loss(float* out, int out_size) {
    if (out_size <= N_TOK * NC_DIM) return;
    if (threadIdx.x == 0 && blockIdx.x == 0) {
        float s = 0.f;
        for (int e = 0; e < E_NUM; e++)
            s += ((float)g_count[e] / (float)N_TOK) * (g_probsum[e] / (float)N_TOK);
        out[(size_t)N_TOK * NC_DIM] = s * (float)E_NUM;
    }
}

// ------- fp16 GEMM: CTA 128x128, BK=64, 2-stage, mixed accum --------------
// main hh -> fp32 acc; cross hl+lh -> shared fp16 acc
#define OFF_ALO 16384
#define OFF_BHI 32768
#define OFF_BLO 49152
#define STGB 65536
#define GEMM_SMEM (2*STGB + 128)

__device__ __forceinline__ float gelu_fast(float v) {
    float u = 0.7978845608028654f * (v + 0.044715f * v * v * v);
    float t;
    asm("tanh.approx.f32 %0, %1;" : "=f"(t) : "f"(u));
    return 0.5f * v * (1.f + t);
}
__device__ __forceinline__ uint32_t swz(int row, int c) {
    return (uint32_t)(row * 128 + ((c ^ (row & 7)) << 4));
}

template <int MODE>
__global__ void __launch_bounds__(256, 1) k_mgemm(
    const fp16* __restrict__ Ahi, const fp16* __restrict__ Alo, size_t sAe,
    const fp16* __restrict__ Bhi, const fp16* __restrict__ Blo, size_t sBe,
    const float* __restrict__ bias, int sBiasE,
    void* __restrict__ out0, void* __restrict__ out1, size_t sCe,
    int K, int ldc, int colmax)
{
    int e = blockIdx.z;
    int m0 = blockIdx.y * 128, n0 = blockIdx.x * 128;
    if (MODE < 2) {
        int c = g_count[e]; if (c > CAP) c = CAP;
        if (m0 >= c) return;
    }
    Ahi += (size_t)e * sAe; Alo += (size_t)e * sAe;
    Bhi += (size_t)e * sBe; Blo += (size_t)e * sBe;
    bias += (size_t)e * sBiasE;

    extern __shared__ char smem_raw[];
    uint32_t base = (smem_u32(smem_raw) + 127) & ~127u;

    int tid = threadIdx.x, lane = tid & 31, wid = tid >> 5;
    int wm = (wid >> 1) * 32, wn = (wid & 1) * 64;   // warp 32x64

    float accf[2][8][4];
    uint32_t acch[2][8][2];
#pragma unroll
    for (int i = 0; i < 2; i++)
#pragma unroll
        for (int j = 0; j < 8; j++) {
#pragma unroll
            for (int q = 0; q < 4; q++) accf[i][j][q] = 0.f;
            acch[i][j][0] = 0u; acch[i][j][1] = 0u;
        }

    int nch = K >> 6;

    auto load_a = [&](int s, int c) {
        if (c >= nch) return;
        uint32_t stg = base + s * STGB;
        int k0 = c << 6;
#pragma unroll
        for (int it = 0; it < 4; it++) {
            int i = tid + it * 256;
            int row = i >> 3, cc = i & 7;
            uint32_t o = swz(row, cc);
            size_t gi = (size_t)(m0 + row) * K + k0 + cc * 8;
            cpa(stg + o, Ahi + gi);
            cpa(stg + OFF_ALO + o, Alo + gi);
        }
    };
    auto load_b = [&](int s, int c) {
        if (c >= nch) return;
        uint32_t stg = base + s * STGB;
        int k0 = c << 6;
#pragma unroll
        for (int it = 0; it < 4; it++) {
            int i = tid + it * 256;
            int row = i >> 3, cc = i & 7;
            uint32_t o = swz(row, cc);
            size_t gi = (size_t)(n0 + row) * K + k0 + cc * 8;
            cpa(stg + OFF_BHI + o, Bhi + gi);
            cpa(stg + OFF_BLO + o, Blo + gi);
        }
    };

    auto compute_ks = [&](int ks, uint32_t stg) {
        uint32_t ah[2][4], al[2][4];
        int ar = wm + (lane & 15);
        int ac = ks * 2 + (lane >> 4);
#pragma unroll
        for (int i = 0; i < 2; i++) {
            uint32_t adr = stg + swz(ar + i * 16, ac);
            ldsm4(ah[i], adr);
            ldsm4(al[i], adr + OFF_ALO);
        }
        int jj = (lane >> 4);
        int brr = wn + (lane & 7);
        int bcc = ks * 2 + ((lane >> 3) & 1);
#pragma unroll
        for (int j2 = 0; j2 < 4; j2++) {
            uint32_t bh[4], bl[4];
            uint32_t adr = stg + OFF_BHI + swz(brr + (j2 * 2 + jj) * 8, bcc);
            ldsm4(bh, adr);
            ldsm4(bl, adr + 16384);
            int ja = j2 * 2, jb = ja + 1;
            // main terms (fp32 accum)
#pragma unroll
            for (int i = 0; i < 2; i++) mma_f32acc(accf[i][ja], ah[i], bh + 0);
#pragma unroll
            for (int i = 0; i < 2; i++) mma_f32acc(accf[i][jb], ah[i], bh + 2);
            // cross terms (fp16 accum, shared accumulator)
#pragma unroll
            for (int i = 0; i < 2; i++) mma_f16acc(acch[i][ja], ah[i], bl + 0);
#pragma unroll
            for (int i = 0; i < 2; i++) mma_f16acc(acch[i][jb], ah[i], bl + 2);
#pragma unroll
            for (int i = 0; i < 2; i++) mma_f16acc(acch[i][ja], al[i], bh + 0);
#pragma unroll
            for (int i = 0; i < 2; i++) mma_f16acc(acch[i][jb], al[i], bh + 2);
        }
    };

    load_a(0, 0); load_b(0, 0); cpa_commit();

    for (int c = 0; c < nch; c++) {
        int s = c & 1;
        uint32_t stg = base + s * STGB;
        cpa_wait<0>();
        __syncthreads();
        compute_ks(0, stg);
        load_a(s ^ 1, c + 1);
        compute_ks(1, stg);
        load_b(s ^ 1, c + 1);
        cpa_commit();
        compute_ks(2, stg);
        compute_ks(3, stg);
    }

    int rb = m0 + wm, cb = n0 + wn;
#pragma unroll
    for (int i = 0; i < 2; i++)
#pragma unroll
        for (int j = 0; j < 8; j++) {
            int r0 = rb + i * 16 + (lane >> 2);
            int c0 = cb + j * 8 + (lane & 3) * 2;
            float bx = bias[c0], by = bias[c0 + 1];
#pragma unroll
            for (int h = 0; h < 2; h++) {
                int row = r0 + h * 8;
                half2 ch = *(half2*)&acch[i][j][h];
                float2 cf = __half22float2(ch);
                float v0 = accf[i][j][h * 2 + 0] + cf.x + bx;
                float v1 = accf[i][j][h * 2 + 1] + cf.y + by;
                if (MODE == 0) {
                    size_t o = (size_t)e * sCe + (size_t)row * ldc + c0;
                    v0 = gelu_fast(v0); v1 = gelu_fast(v1);
                    split2(v0, v1, (fp16*)out0 + o, (fp16*)out1 + o);
                } else if (MODE == 1) {
                    int t = g_inv[e * CAP + row];
                    if (t >= 0) {
                        float g = g_gate[t];
                        size_t o = (size_t)t * ldc + c0;
                        split2(v0 * g, v1 * g, (fp16*)out0 + o, (fp16*)out1 + o);
                    }
                } else {
                    size_t oo = (size_t)row * ldc + c0;
                    if (c0 < colmax)     ((float*)out0)[oo] = v0;
                    if (c0 + 1 < colmax) ((float*)out0)[oo + 1] = v1;
                }
            }
        }
}

// ---------------- launch ----------------
extern "C" void kernel_launch(void* const* d_in, const int* in_sizes, int n_in,
                              void* d_out, int out_size) {
    const float* x  = (const float*)d_in[0];
    const float* Wg = (const float*)d_in[1];
    const float* W1 = (const float*)d_in[2];
    const float* b1 = (const float*)d_in[3];
    const float* W2 = (const float*)d_in[4];
    const float* b2 = (const float*)d_in[5];
    const float* Wl = (const float*)d_in[6];
    const float* bl = (const float*)d_in[7];
    float* out = (float*)d_out;

    static cudaStream_t sB = nullptr;
    static cudaEvent_t evFork, evW1, evW2, evWl;
    static int init_done = 0;
    if (!init_done) {
        cudaFuncSetAttribute((const void*)k_mgemm<0>, cudaFuncAttributeMaxDynamicSharedMemorySize, GEMM_SMEM);
        cudaFuncSetAttribute((const void*)k_mgemm<1>, cudaFuncAttributeMaxDynamicSharedMemorySize, GEMM_SMEM);
        cudaFuncSetAttribute((const void*)k_mgemm<2>, cudaFuncAttributeMaxDynamicSharedMemorySize, GEMM_SMEM);
        cudaStreamCreateWithFlags(&sB, cudaStreamNonBlocking);
        cudaEventCreateWithFlags(&evFork, cudaEventDisableTiming);
        cudaEventCreateWithFlags(&evW1, cudaEventDisableTiming);
        cudaEventCreateWithFlags(&evW2, cudaEventDisableTiming);
        cudaEventCreateWithFlags(&evWl, cudaEventDisableTiming);
        init_done = 1;
    }

    fp16 *w1h, *w1l, *w2h, *w2l, *wlh, *wll, *dh, *dl, *hh, *hl, *yh, *yl;
    cudaGetSymbolAddress((void**)&w1h, g_w1t_hi); cudaGetSymbolAddress((void**)&w1l, g_w1t_lo);
    cudaGetSymbolAddress((void**)&w2h, g_w2t_hi); cudaGetSymbolAddress((void**)&w2l, g_w2t_lo);
    cudaGetSymbolAddress((void**)&wlh, g_wlt_hi); cudaGetSymbolAddress((void**)&wll, g_wlt_lo);
    cudaGetSymbolAddress((void**)&dh, g_disp_hi); cudaGetSymbolAddress((void**)&dl, g_disp_lo);
    cudaGetSymbolAddress((void**)&hh, g_h_hi);    cudaGetSymbolAddress((void**)&hl, g_h_lo);
    cudaGetSymbolAddress((void**)&yh, g_y_hi);    cudaGetSymbolAddress((void**)&yl, g_y_lo);

    // stream B: weight splits (independent of routing)
    cudaEventRecord(evFork, 0);
    cudaStreamWaitEvent(sB, evFork, 0);
    k_ws1<<<dim3(H_DIM/32, D_DIM/32, E_NUM), 256, 0, sB>>>(W1);
    cudaEventRecord(evW1, sB);
    k_ws2<<<dim3(D_DIM/32, H_DIM/32, E_NUM), 256, 0, sB>>>(W2);
    cudaEventRecord(evW2, sB);
    k_wsl<<<dim3(1024/32, D_DIM/32, 1), 256, 0, sB>>>(Wl);
    cudaEventRecord(evWl, sB);

    // stream 0: routing
    k_wgt<<<64, 256>>>(Wg);
    k_gate<<<NB_GATE, 256>>>(x);
    k_scan<<<E_NUM, 256>>>();
    k_dispatch<<<N_TOK, 256>>>(x);

    // FFN1
    cudaStreamWaitEvent(0, evW1, 0);
    k_mgemm<0><<<dim3(H_DIM/128, CAP/128, E_NUM), 256, GEMM_SMEM>>>(
        dh, dl, (size_t)CAP*D_DIM, w1h, w1l, (size_t)H_DIM*D_DIM,
        b1, H_DIM, hh, hl, (size_t)CAP*H_DIM, D_DIM, H_DIM, H_DIM);

    // FFN2 -> fused combine into y
    cudaStreamWaitEvent(0, evW2, 0);
    k_mgemm<1><<<dim3(D_DIM/128, CAP/128, E_NUM), 256, GEMM_SMEM>>>(
        hh, hl, (size_t)CAP*H_DIM, w2h, w2l, (size_t)D_DIM*H_DIM,
        b2, D_DIM, yh, yl, 0, H_DIM, D_DIM, D_DIM);

    // classifier
    cudaStreamWaitEvent(0, evWl, 0);
    k_mgemm<2><<<dim3(1024/128, N_TOK/128, 1), 256, GEMM_SMEM>>>(
        yh, yl, 0, wlh, wll, 0,
        bl, 0, out, nullptr, 0, D_DIM, NC_DIM, NC_DIM);

    k_loss<<<1, 32>>>(out, out_size);
}

// round 15
// speedup vs baseline: 1.0649x; 1.0649x over previous
#include <cuda_runtime.h>
#include <cuda_bf16.h>
#include <math.h>
#include <stdint.h>

#define N_TOK 16384
#define D_DIM 1024
#define E_NUM 16
#define H_DIM 4096
#define NC_DIM 1000
#define CAP 2048
#define NB_GATE (N_TOK/8)

typedef __nv_bfloat16 bf16;

// ---------------- device scratch ----------------
__device__ __align__(16) bf16 g_disp_hi[(size_t)E_NUM*CAP*D_DIM];
__device__ __align__(16) bf16 g_disp_lo[(size_t)E_NUM*CAP*D_DIM];
__device__ __align__(16) bf16 g_h_hi[(size_t)E_NUM*CAP*H_DIM];
__device__ __align__(16) bf16 g_h_lo[(size_t)E_NUM*CAP*H_DIM];
__device__ __align__(16) bf16 g_y_hi[(size_t)N_TOK*D_DIM];
__device__ __align__(16) bf16 g_y_lo[(size_t)N_TOK*D_DIM];
__device__ __align__(16) bf16 g_w1t_hi[(size_t)E_NUM*H_DIM*D_DIM];
__device__ __align__(16) bf16 g_w1t_lo[(size_t)E_NUM*H_DIM*D_DIM];
__device__ __align__(16) bf16 g_w2t_hi[(size_t)E_NUM*D_DIM*H_DIM];
__device__ __align__(16) bf16 g_w2t_lo[(size_t)E_NUM*D_DIM*H_DIM];
__device__ __align__(16) bf16 g_wlt_hi[(size_t)1024*D_DIM];
__device__ __align__(16) bf16 g_wlt_lo[(size_t)1024*D_DIM];
__device__ __align__(16) float g_wgt[16*1024];       // Wg transposed [e][d]
__device__ int   g_idx[N_TOK];
__device__ float g_gate[N_TOK];
__device__ int   g_lrank[N_TOK];
__device__ int   g_bhist[NB_GATE][E_NUM];
__device__ float g_bprob[NB_GATE][E_NUM];
__device__ int   g_boff[NB_GATE][E_NUM];
__device__ int   g_count[E_NUM];
__device__ float g_probsum[E_NUM];
__device__ int   g_inv[E_NUM*CAP];

// ---------------- PTX helpers ----------------
__device__ __forceinline__ uint32_t smem_u32(const void* p) {
    return (uint32_t)__cvta_generic_to_shared(p);
}
__device__ __forceinline__ void cpa(uint32_t dst, const void* src) {
    asm volatile("cp.async.cg.shared.global [%0], [%1], 16;" :: "r"(dst), "l"(src) : "memory");
}
__device__ __forceinline__ void cpa_commit() { asm volatile("cp.async.commit_group;" ::: "memory"); }
template<int N> __device__ __forceinline__ void cpa_wait() {
    asm volatile("cp.async.wait_group %0;" :: "n"(N) : "memory");
}
__device__ __forceinline__ void ldsm4(uint32_t* r, uint32_t a) {
    asm volatile("ldmatrix.sync.aligned.m8n8.x4.shared.b16 {%0,%1,%2,%3}, [%4];"
                 : "=r"(r[0]), "=r"(r[1]), "=r"(r[2]), "=r"(r[3]) : "r"(a));
}
__device__ __forceinline__ void mma_bf16(float* d, const uint32_t* a, const uint32_t* b) {
    asm volatile(
        "mma.sync.aligned.m16n8k16.row.col.f32.bf16.bf16.f32 "
        "{%0,%1,%2,%3}, {%4,%5,%6,%7}, {%8,%9}, {%0,%1,%2,%3};"
        : "+f"(d[0]), "+f"(d[1]), "+f"(d[2]), "+f"(d[3])
        : "r"(a[0]), "r"(a[1]), "r"(a[2]), "r"(a[3]), "r"(b[0]), "r"(b[1]));
}

// packed hi/lo split
__device__ __forceinline__ void split2u(float a, float b, uint32_t& hi, uint32_t& lo) {
    __nv_bfloat162 h = __float22bfloat162_rn(make_float2(a, b));
    hi = *(uint32_t*)&h;
    float2 hf = __bfloat1622float2(h);
    __nv_bfloat162 l = __float22bfloat162_rn(make_float2(a - hf.x, b - hf.y));
    lo = *(uint32_t*)&l;
}
__device__ __forceinline__ void split2(float a, float b, bf16* hi, bf16* lo) {
    uint32_t h, l;
    split2u(a, b, h, l);
    *(uint32_t*)hi = h; *(uint32_t*)lo = l;
}

// ---------------- Wg transpose ----------------
__global__ void k_wgt(const float* __restrict__ Wg) {
    int i = blockIdx.x * 256 + threadIdx.x;
    int d = i >> 4, e = i & 15;
    g_wgt[e * 1024 + d] = Wg[i];
}

// ---------------- gating: coalesced float4 reads of WgT ----------------
__global__ void k_gate(const float* __restrict__ x) {
    int warp = threadIdx.x >> 5, lane = threadIdx.x & 31;
    int t = blockIdx.x * 8 + warp;
    __shared__ float s_prob[E_NUM];
    __shared__ int s_idx[8];
    if (threadIdx.x < E_NUM) s_prob[threadIdx.x] = 0.f;
    __syncthreads();
    float acc[E_NUM];
#pragma unroll
    for (int e = 0; e < E_NUM; e++) acc[e] = 0.f;
    const float4* xr = (const float4*)(x + (size_t)t * D_DIM);
    const float4* wt = (const float4*)g_wgt;
#pragma unroll
    for (int j = 0; j < 8; j++) {
        int i = lane + 32 * j;
        float4 xv = xr[i];
#pragma unroll
        for (int e = 0; e < E_NUM; e++) {
            float4 w = __ldg(wt + (size_t)e * 256 + i);
            acc[e] = fmaf(xv.x, w.x, fmaf(xv.y, w.y,
                     fmaf(xv.z, w.z, fmaf(xv.w, w.w, acc[e]))));
        }
    }
#pragma unroll
    for (int e = 0; e < E_NUM; e++)
#pragma unroll
        for (int o = 16; o > 0; o >>= 1) acc[e] += __shfl_xor_sync(0xffffffffu, acc[e], o);
    if (lane == 0) {
        float m = acc[0]; int ai = 0;
#pragma unroll
        for (int e = 1; e < E_NUM; e++) if (acc[e] > m) { m = acc[e]; ai = e; }
        float p[E_NUM]; float s = 0.f;
#pragma unroll
        for (int e = 0; e < E_NUM; e++) { p[e] = expf(acc[e] - m); s += p[e]; }
        float inv = 1.f / s;
#pragma unroll
        for (int e = 0; e < E_NUM; e++) atomicAdd(&s_prob[e], p[e] * inv);
        g_idx[t] = ai; g_gate[t] = p[ai] * inv; s_idx[warp] = ai;
    }
    __syncthreads();
    if (threadIdx.x == 0) {
        int cnt[E_NUM];
#pragma unroll
        for (int e = 0; e < E_NUM; e++) cnt[e] = 0;
#pragma unroll
        for (int w = 0; w < 8; w++) {
            int e = s_idx[w];
            g_lrank[blockIdx.x * 8 + w] = cnt[e];
            cnt[e]++;
        }
#pragma unroll
        for (int e = 0; e < E_NUM; e++) g_bhist[blockIdx.x][e] = cnt[e];
    }
    if (threadIdx.x < E_NUM) g_bprob[blockIdx.x][threadIdx.x] = s_prob[threadIdx.x];
}

// ---------------- scan + probsum reduce + pad ----------------
__global__ void k_scan() {
    const int PB = NB_GATE / 256;
    int e = blockIdx.x, tid = threadIdx.x;
    int v[PB]; int s = 0;
    float ps = 0.f;
#pragma unroll
    for (int i = 0; i < PB; i++) {
        v[i] = g_bhist[tid * PB + i][e];
        s += v[i];
        ps += g_bprob[tid * PB + i][e];
    }
    __shared__ int sh[256];
    __shared__ float sp[256];
    sh[tid] = s; sp[tid] = ps;
    __syncthreads();
    for (int o = 1; o < 256; o <<= 1) {
        int q = (tid >= o) ? sh[tid - o] : 0;
        __syncthreads(); sh[tid] += q; __syncthreads();
    }
    int off = sh[tid] - s;
#pragma unroll
    for (int i = 0; i < PB; i++) { g_boff[tid * PB + i][e] = off; off += v[i]; }
    for (int o = 128; o > 0; o >>= 1) {
        if (tid < o) sp[tid] += sp[tid + o];
        __syncthreads();
    }
    if (tid == 0) { g_count[e] = sh[255]; g_probsum[e] = sp[0]; }
    __syncthreads();
    int c = sh[255]; if (c > CAP) c = CAP;
    int r1 = (c + 127) & ~127; if (r1 > CAP) r1 = CAP;
    for (int r = c; r < r1; r++) {
        size_t b = ((size_t)e * CAP + r) * D_DIM + tid * 4;
        *(float2*)(g_disp_hi + b) = make_float2(0.f, 0.f);
        *(float2*)(g_disp_lo + b) = make_float2(0.f, 0.f);
    }
    for (int r = c + tid; r < r1; r += 256) g_inv[e * CAP + r] = -1;
}

// wsplit: in [E,R,C] fp32 -> out [E,Cpad,R] bf16 hi/lo
// tile: 64 R-rows x 32 C-cols; each thread emits one 16B store per array
// (8 consecutive R per output row) -> full 128B sectors per output row
__device__ __forceinline__ void wsplit_body(
    const float* __restrict__ in, bf16* __restrict__ ohi, bf16* __restrict__ olo,
    int R, int C, int Cpad, int bx, int by, int bz, int tid)
{
    __shared__ float s[64][33];
    const float* ip = in + (size_t)bz * R * C;
    size_t ob = (size_t)bz * Cpad * R;
    int c0 = bx * 32, r0 = by * 64;
    int tx = tid & 31, ty = tid >> 5;
#pragma unroll
    for (int k = 0; k < 8; k++) {
        int r = r0 + ty + 8 * k, c = c0 + tx;
        s[ty + 8 * k][tx] = (c < C) ? ip[(size_t)r * C + c] : 0.f;
    }
    __syncthreads();
    // thread -> column n = c0 + (tid>>3); 8 consecutive rows from (tid&7)*8
    int cl = tid >> 3, rg = (tid & 7) * 8;
    int n = c0 + cl;
    uint32_t h[4], l[4];
#pragma unroll
    for (int q = 0; q < 4; q++)
        split2u(s[rg + 2*q][cl], s[rg + 2*q + 1][cl], h[q], l[q]);
    size_t o = ob + (size_t)n * R + r0 + rg;
    *(uint4*)(ohi + o) = make_uint4(h[0], h[1], h[2], h[3]);
    *(uint4*)(olo + o) = make_uint4(l[0], l[1], l[2], l[3]);
}

__global__ void k_ws1(const float* __restrict__ W1) {
    wsplit_body(W1, g_w1t_hi, g_w1t_lo, D_DIM, H_DIM, H_DIM,
                blockIdx.x, blockIdx.y, blockIdx.z, threadIdx.x);
}
__global__ void k_ws2(const float* __restrict__ W2) {
    wsplit_body(W2, g_w2t_hi, g_w2t_lo, H_DIM, D_DIM, D_DIM,
                blockIdx.x, blockIdx.y, blockIdx.z, threadIdx.x);
}
__global__ void k_wsl(const float* __restrict__ Wl) {
    wsplit_body(Wl, g_wlt_hi, g_wlt_lo, D_DIM, NC_DIM, 1024,
                blockIdx.x, blockIdx.y, 0, threadIdx.x);
}

// dispatch + (tail block) balancing loss
__global__ void k_dispatch(const float* __restrict__ x, float* out, int out_size) {
    int b = blockIdx.x, tid = threadIdx.x;
    if (b >= N_TOK) {   // loss block
        if (tid == 0 && out_size > N_TOK * NC_DIM) {
            float s = 0.f;
            for (int e = 0; e < E_NUM; e++)
                s += ((float)g_count[e] / (float)N_TOK) * (g_probsum[e] / (float)N_TOK);
            out[(size_t)N_TOK * NC_DIM] = s * (float)E_NUM;
        }
        return;
    }
    int t = b;
    int e = g_idx[t];
    int pos = g_boff[t >> 3][e] + g_lrank[t];
    if (pos < CAP) {
        if (tid == 0) g_inv[e * CAP + pos] = t;
        float4 v = ((const float4*)(x + (size_t)t * D_DIM))[tid];
        size_t o = ((size_t)e * CAP + pos) * D_DIM + tid * 4;
        uint32_t h01, l01, h23, l23;
        split2u(v.x, v.y, h01, l01);
        split2u(v.z, v.w, h23, l23);
        *(uint2*)(g_disp_hi + o) = make_uint2(h01, h23);
        *(uint2*)(g_disp_lo + o) = make_uint2(l01, l23);
    } else {
        size_t o = (size_t)t * D_DIM + tid * 4;
        *(float2*)(g_y_hi + o) = make_float2(0.f, 0.f);
        *(float2*)(g_y_lo + o) = make_float2(0.f, 0.f);
    }
}

// ------------- mma.sync bf16 GEMM: CTA 128xNT, BK=64, 2-stage, 1 sync/chunk
#define OFF_ALO 16384
#define OFF_BHI 32768

__device__ __forceinline__ float gelu_fast(float v) {
    float u = 0.7978845608028654f * (v + 0.044715f * v * v * v);
    float t;
    asm("tanh.approx.f32 %0, %1;" : "=f"(t) : "f"(u));
    return 0.5f * v * (1.f + t);
}
__device__ __forceinline__ uint32_t swz(int row, int c) {
    return (uint32_t)(row * 128 + ((c ^ (row & 7)) << 4));
}

template <int MODE, int WI>
__global__ void __launch_bounds__(256, 1) k_mgemm(
    const bf16* __restrict__ Ahi, const bf16* __restrict__ Alo, size_t sAe,
    const bf16* __restrict__ Bhi, const bf16* __restrict__ Blo, size_t sBe,
    const float* __restrict__ bias, int sBiasE,
    void* __restrict__ out0, void* __restrict__ out1, size_t sCe,
    int K, int ldc, int colmax)
{
    constexpr int NT = WI * 64;
    constexpr int STGB = OFF_BHI + 2 * NT * 128;

    int e = blockIdx.z;
    int m0 = blockIdx.y * 128, n0 = blockIdx.x * NT;
    if (MODE < 2) {
        int c = g_count[e]; if (c > CAP) c = CAP;
        if (m0 >= c) return;
    }
    Ahi += (size_t)e * sAe; Alo += (size_t)e * sAe;
    Bhi += (size_t)e * sBe; Blo += (size_t)e * sBe;
    bias += (size_t)e * sBiasE;

    extern __shared__ char smem_raw[];
    uint32_t base = (smem_u32(smem_raw) + 127) & ~127u;

    int tid = threadIdx.x, lane = tid & 31, wid = tid >> 5;
    int wm, wn;
    if (WI == 4) { wm = (wid >> 2) * 64; wn = (wid & 3) * 64; }
    else         { wm = (wid >> 1) * 32; wn = (wid & 1) * 64; }

    float acc[WI][8][4];
#pragma unroll
    for (int i = 0; i < WI; i++)
#pragma unroll
        for (int j = 0; j < 8; j++)
#pragma unroll
            for (int q = 0; q < 4; q++) acc[i][j][q] = 0.f;

    int nch = K >> 6;

    auto load_a = [&](int s, int c) {
        if (c >= nch) return;
        uint32_t stg = base + s * STGB;
        int k0 = c << 6;
#pragma unroll
        for (int it = 0; it < 4; it++) {
            int i = tid + it * 256;
            int row = i >> 3, cc = i & 7;
            uint32_t o = swz(row, cc);
            size_t gi = (size_t)(m0 + row) * K + k0 + cc * 8;
            cpa(stg + o, Ahi + gi);
            cpa(stg + OFF_ALO + o, Alo + gi);
        }
    };
    auto load_bh = [&](int s, int c) {
        if (c >= nch) return;
        uint32_t stg = base + s * STGB;
        int k0 = c << 6;
#pragma unroll
        for (int it = 0; it < NT / 32; it++) {
            int i = tid + it * 256;
            int row = i >> 3, cc = i & 7;
            size_t gi = (size_t)(n0 + row) * K + k0 + cc * 8;
            cpa(stg + OFF_BHI + swz(row, cc), Bhi + gi);
        }
    };
    auto load_bl = [&](int s, int c) {
        if (c >= nch) return;
        uint32_t stg = base + s * STGB;
        int k0 = c << 6;
#pragma unroll
        for (int it = 0; it < NT / 32; it++) {
            int i = tid + it * 256;
            int row = i >> 3, cc = i & 7;
            size_t gi = (size_t)(n0 + row) * K + k0 + cc * 8;
            cpa(stg + OFF_BHI + NT * 128 + swz(row, cc), Blo + gi);
        }
    };

    auto compute_ks = [&](int ks, uint32_t stg) {
        uint32_t ah[WI][4], al[WI][4];
        int ar = wm + (lane & 15);
        int ac = ks * 2 + (lane >> 4);
#pragma unroll
        for (int i = 0; i < WI; i++) {
            uint32_t adr = stg + swz(ar + i * 16, ac);
            ldsm4(ah[i], adr);
            ldsm4(al[i], adr + OFF_ALO);
        }
        int jj = (lane >> 4);
        int brr = wn + (lane & 7);
        int bcc = ks * 2 + ((lane >> 3) & 1);
#pragma unroll
        for (int j2 = 0; j2 < 4; j2++) {
            uint32_t bh[4], bl[4];
            uint32_t adr = stg + OFF_BHI + swz(brr + (j2 * 2 + jj) * 8, bcc);
            ldsm4(bh, adr);
            ldsm4(bl, adr + NT * 128);
            int ja = j2 * 2, jb = ja + 1;
#pragma unroll
            for (int i = 0; i < WI; i++) mma_bf16(acc[i][ja], ah[i], bh + 0);
#pragma unroll
            for (int i = 0; i < WI; i++) mma_bf16(acc[i][jb], ah[i], bh + 2);
#pragma unroll
            for (int i = 0; i < WI; i++) mma_bf16(acc[i][ja], ah[i], bl + 0);
#pragma unroll
            for (int i = 0; i < WI; i++) mma_bf16(acc[i][jb], ah[i], bl + 2);
#pragma unroll
            for (int i = 0; i < WI; i++) mma_bf16(acc[i][ja], al[i], bh + 0);
#pragma unroll
            for (int i = 0; i < WI; i++) mma_bf16(acc[i][jb], al[i], bh + 2);
        }
    };

    load_a(0, 0); load_bh(0, 0); load_bl(0, 0); cpa_commit();

    for (int c = 0; c < nch; c++) {
        int s = c & 1;
        uint32_t stg = base + s * STGB;
        cpa_wait<0>();
        __syncthreads();
        compute_ks(0, stg);
        load_a(s ^ 1, c + 1);
        load_bh(s ^ 1, c + 1);
        compute_ks(1, stg);
        load_bl(s ^ 1, c + 1);
        cpa_commit();
        compute_ks(2, stg);
        compute_ks(3, stg);
    }

    int rb = m0 + wm, cb = n0 + wn;
#pragma unroll
    for (int i = 0; i < WI; i++)
#pragma unroll
        for (int j = 0; j < 8; j++) {
            int r0 = rb + i * 16 + (lane >> 2);
            int c0 = cb + j * 8 + (lane & 3) * 2;
            float bx = bias[c0], by = bias[c0 + 1];
#pragma unroll
            for (int h = 0; h < 2; h++) {
                int row = r0 + h * 8;
                float v0 = acc[i][j][h * 2 + 0] + bx;
                float v1 = acc[i][j][h * 2 + 1] + by;
                if (MODE == 0) {
                    size_t o = (size_t)e * sCe + (size_t)row * ldc + c0;
                    v0 = gelu_fast(v0); v1 = gelu_fast(v1);
                    split2(v0, v1, (bf16*)out0 + o, (bf16*)out1 + o);
                } else if (MODE == 1) {
                    int t = g_inv[e * CAP + row];
                    if (t >= 0) {
                        float g = g_gate[t];
                        size_t o = (size_t)t * ldc + c0;
                        split2(v0 * g, v1 * g, (bf16*)out0 + o, (bf16*)out1 + o);
                    }
                } else {
                    size_t oo = (size_t)row * ldc + c0;
                    if (c0 < colmax)     ((float*)out0)[oo] = v0;
                    if (c0 + 1 < colmax) ((float*)out0)[oo + 1] = v1;
                }
            }
        }
}

// ---------------- launch ----------------
extern "C" void kernel_launch(void* const* d_in, const int* in_sizes, int n_in,
                              void* d_out, int out_size) {
    const float* x  = (const float*)d_in[0];
    const float* Wg = (const float*)d_in[1];
    const float* W1 = (const float*)d_in[2];
    const float* b1 = (const float*)d_in[3];
    const float* W2 = (const float*)d_in[4];
    const float* b2 = (const float*)d_in[5];
    const float* Wl = (const float*)d_in[6];
    const float* bl = (const float*)d_in[7];
    float* out = (float*)d_out;

    const int GEMM_SMEM4 = 2 * (32768 + 2 * 256 * 128) + 128;  // 196736
    const int GEMM_SMEM2 = 2 * (32768 + 2 * 128 * 128) + 128;  // 131200

    static cudaStream_t sB = nullptr;
    static cudaEvent_t evFork, evW1, evW2, evWl;
    static int init_done = 0;
    if (!init_done) {
        cudaFuncSetAttribute((const void*)k_mgemm<0,4>, cudaFuncAttributeMaxDynamicSharedMemorySize, GEMM_SMEM4);
        cudaFuncSetAttribute((const void*)k_mgemm<1,4>, cudaFuncAttributeMaxDynamicSharedMemorySize, GEMM_SMEM4);
        cudaFuncSetAttribute((const void*)k_mgemm<2,2>, cudaFuncAttributeMaxDynamicSharedMemorySize, GEMM_SMEM2);
        cudaStreamCreateWithFlags(&sB, cudaStreamNonBlocking);
        cudaEventCreateWithFlags(&evFork, cudaEventDisableTiming);
        cudaEventCreateWithFlags(&evW1, cudaEventDisableTiming);
        cudaEventCreateWithFlags(&evW2, cudaEventDisableTiming);
        cudaEventCreateWithFlags(&evWl, cudaEventDisableTiming);
        init_done = 1;
    }

    bf16 *w1h, *w1l, *w2h, *w2l, *wlh, *wll, *dh, *dl, *hh, *hl, *yh, *yl;
    cudaGetSymbolAddress((void**)&w1h, g_w1t_hi); cudaGetSymbolAddress((void**)&w1l, g_w1t_lo);
    cudaGetSymbolAddress((void**)&w2h, g_w2t_hi); cudaGetSymbolAddress((void**)&w2l, g_w2t_lo);
    cudaGetSymbolAddress((void**)&wlh, g_wlt_hi); cudaGetSymbolAddress((void**)&wll, g_wlt_lo);
    cudaGetSymbolAddress((void**)&dh, g_disp_hi); cudaGetSymbolAddress((void**)&dl, g_disp_lo);
    cudaGetSymbolAddress((void**)&hh, g_h_hi);    cudaGetSymbolAddress((void**)&hl, g_h_lo);
    cudaGetSymbolAddress((void**)&yh, g_y_hi);    cudaGetSymbolAddress((void**)&yl, g_y_lo);

    // fork stream B for weight splits (independent of routing)
    cudaEventRecord(evFork, 0);
    cudaStreamWaitEvent(sB, evFork, 0);
    k_ws1<<<dim3(H_DIM/32, D_DIM/64, E_NUM), 256, 0, sB>>>(W1);
    cudaEventRecord(evW1, sB);
    k_ws2<<<dim3(D_DIM/32, H_DIM/64, E_NUM), 256, 0, sB>>>(W2);
    cudaEventRecord(evW2, sB);
    k_wsl<<<dim3(1024/32, D_DIM/64, 1), 256, 0, sB>>>(Wl);
    cudaEventRecord(evWl, sB);

    // stream 0: routing chain
    k_wgt<<<64, 256>>>(Wg);
    k_gate<<<NB_GATE, 256>>>(x);
    k_scan<<<E_NUM, 256>>>();
    k_dispatch<<<N_TOK + 1, 256>>>(x, out, out_size);

    // FFN1 (needs W1 split + dispatch)
    cudaStreamWaitEvent(0, evW1, 0);
    k_mgemm<0,4><<<dim3(H_DIM/256, CAP/128, E_NUM), 256, GEMM_SMEM4>>>(
        dh, dl, (size_t)CAP*D_DIM, w1h, w1l, (size_t)H_DIM*D_DIM,
        b1, H_DIM, hh, hl, (size_t)CAP*H_DIM, D_DIM, H_DIM, H_DIM);

    // FFN2 (NT=256) -> fused combine into y
    cudaStreamWaitEvent(0, evW2, 0);
    k_mgemm<1,4><<<dim3(D_DIM/256, CAP/128, E_NUM), 256, GEMM_SMEM4>>>(
        hh, hl, (size_t)CAP*H_DIM, w2h, w2l, (size_t)D_DIM*H_DIM,
        b2, D_DIM, yh, yl, 0, H_DIM, D_DIM, D_DIM);

    // classifier
    cudaStreamWaitEvent(0, evWl, 0);
    k_mgemm<2,2><<<dim3(1024/128, N_TOK/128, 1), 256, GEMM_SMEM2>>>(
        yh, yl, 0, wlh, wll, 0,
        bl, 0, out, nullptr, 0, D_DIM, NC_DIM, NC_DIM);
}

// round 16
// speedup vs baseline: 1.4487x; 1.3603x over previous
#include <cuda_runtime.h>
#include <cuda_fp16.h>
#include <math.h>
#include <stdint.h>

#define N_TOK 16384
#define D_DIM 1024
#define E_NUM 16
#define H_DIM 4096
#define NC_DIM 1000
#define CAP 2048
#define NB_GATE (N_TOK/8)

typedef __half fp16;

// ---------------- device scratch ----------------
__device__ __align__(16) fp16 g_disp[(size_t)E_NUM*CAP*D_DIM];
__device__ __align__(16) fp16 g_h[(size_t)E_NUM*CAP*H_DIM];
__device__ __align__(16) fp16 g_y[(size_t)N_TOK*D_DIM];
__device__ __align__(16) fp16 g_w1t_hi[(size_t)E_NUM*H_DIM*D_DIM];
__device__ __align__(16) fp16 g_w1t_lo[(size_t)E_NUM*H_DIM*D_DIM];
__device__ __align__(16) fp16 g_w2t_hi[(size_t)E_NUM*D_DIM*H_DIM];
__device__ __align__(16) fp16 g_w2t_lo[(size_t)E_NUM*D_DIM*H_DIM];
__device__ __align__(16) fp16 g_wlt_hi[(size_t)1024*D_DIM];
__device__ __align__(16) fp16 g_wlt_lo[(size_t)1024*D_DIM];
__device__ __align__(16) float g_wgt[16*1024];       // Wg transposed [e][d]
__device__ int   g_idx[N_TOK];
__device__ float g_gate[N_TOK];
__device__ int   g_lrank[N_TOK];
__device__ int   g_bhist[NB_GATE][E_NUM];
__device__ float g_bprob[NB_GATE][E_NUM];
__device__ int   g_boff[NB_GATE][E_NUM];
__device__ int   g_count[E_NUM];
__device__ float g_probsum[E_NUM];
__device__ int   g_inv[E_NUM*CAP];

// ---------------- PTX helpers ----------------
__device__ __forceinline__ uint32_t smem_u32(const void* p) {
    return (uint32_t)__cvta_generic_to_shared(p);
}
__device__ __forceinline__ void cpa(uint32_t dst, const void* src) {
    asm volatile("cp.async.cg.shared.global [%0], [%1], 16;" :: "r"(dst), "l"(src) : "memory");
}
__device__ __forceinline__ void cpa_commit() { asm volatile("cp.async.commit_group;" ::: "memory"); }
template<int N> __device__ __forceinline__ void cpa_wait() {
    asm volatile("cp.async.wait_group %0;" :: "n"(N) : "memory");
}
__device__ __forceinline__ void ldsm4(uint32_t* r, uint32_t a) {
    asm volatile("ldmatrix.sync.aligned.m8n8.x4.shared.b16 {%0,%1,%2,%3}, [%4];"
                 : "=r"(r[0]), "=r"(r[1]), "=r"(r[2]), "=r"(r[3]) : "r"(a));
}
__device__ __forceinline__ void mma_f16(float* d, const uint32_t* a, const uint32_t* b) {
    asm volatile(
        "mma.sync.aligned.m16n8k16.row.col.f32.f16.f16.f32 "
        "{%0,%1,%2,%3}, {%4,%5,%6,%7}, {%8,%9}, {%0,%1,%2,%3};"
        : "+f"(d[0]), "+f"(d[1]), "+f"(d[2]), "+f"(d[3])
        : "r"(a[0]), "r"(a[1]), "r"(a[2]), "r"(a[3]), "r"(b[0]), "r"(b[1]));
}

// fp16 hi/lo split (weights)
__device__ __forceinline__ void split2u(float a, float b, uint32_t& hi, uint32_t& lo) {
    half2 h = __float22half2_rn(make_float2(a, b));
    hi = *(uint32_t*)&h;
    float2 hf = __half22float2(h);
    half2 l = __float22half2_rn(make_float2(a - hf.x, b - hf.y));
    lo = *(uint32_t*)&l;
}
// fp16 pack (activations, hi only)
__device__ __forceinline__ uint32_t pack2(float a, float b) {
    half2 h = __float22half2_rn(make_float2(a, b));
    return *(uint32_t*)&h;
}

// ---------------- Wg transpose ----------------
__global__ void k_wgt(const float* __restrict__ Wg) {
    int i = blockIdx.x * 256 + threadIdx.x;
    int d = i >> 4, e = i & 15;
    g_wgt[e * 1024 + d] = Wg[i];
}

// ---------------- gating: coalesced float4 reads of WgT ----------------
__global__ void k_gate(const float* __restrict__ x) {
    int warp = threadIdx.x >> 5, lane = threadIdx.x & 31;
    int t = blockIdx.x * 8 + warp;
    __shared__ float s_prob[E_NUM];
    __shared__ int s_idx[8];
    if (threadIdx.x < E_NUM) s_prob[threadIdx.x] = 0.f;
    __syncthreads();
    float acc[E_NUM];
#pragma unroll
    for (int e = 0; e < E_NUM; e++) acc[e] = 0.f;
    const float4* xr = (const float4*)(x + (size_t)t * D_DIM);
    const float4* wt = (const float4*)g_wgt;
#pragma unroll
    for (int j = 0; j < 8; j++) {
        int i = lane + 32 * j;
        float4 xv = xr[i];
#pragma unroll
        for (int e = 0; e < E_NUM; e++) {
            float4 w = __ldg(wt + (size_t)e * 256 + i);
            acc[e] = fmaf(xv.x, w.x, fmaf(xv.y, w.y,
                     fmaf(xv.z, w.z, fmaf(xv.w, w.w, acc[e]))));
        }
    }
#pragma unroll
    for (int e = 0; e < E_NUM; e++)
#pragma unroll
        for (int o = 16; o > 0; o >>= 1) acc[e] += __shfl_xor_sync(0xffffffffu, acc[e], o);
    if (lane == 0) {
        float m = acc[0]; int ai = 0;
#pragma unroll
        for (int e = 1; e < E_NUM; e++) if (acc[e] > m) { m = acc[e]; ai = e; }
        float p[E_NUM]; float s = 0.f;
#pragma unroll
        for (int e = 0; e < E_NUM; e++) { p[e] = expf(acc[e] - m); s += p[e]; }
        float inv = 1.f / s;
#pragma unroll
        for (int e = 0; e < E_NUM; e++) atomicAdd(&s_prob[e], p[e] * inv);
        g_idx[t] = ai; g_gate[t] = p[ai] * inv; s_idx[warp] = ai;
    }
    __syncthreads();
    if (threadIdx.x == 0) {
        int cnt[E_NUM];
#pragma unroll
        for (int e = 0; e < E_NUM; e++) cnt[e] = 0;
#pragma unroll
        for (int w = 0; w < 8; w++) {
            int e = s_idx[w];
            g_lrank[blockIdx.x * 8 + w] = cnt[e];
            cnt[e]++;
        }
#pragma unroll
        for (int e = 0; e < E_NUM; e++) g_bhist[blockIdx.x][e] = cnt[e];
    }
    if (threadIdx.x < E_NUM) g_bprob[blockIdx.x][threadIdx.x] = s_prob[threadIdx.x];
}

// ---------------- scan + probsum reduce + pad ----------------
__global__ void k_scan() {
    const int PB = NB_GATE / 256;
    int e = blockIdx.x, tid = threadIdx.x;
    int v[PB]; int s = 0;
    float ps = 0.f;
#pragma unroll
    for (int i = 0; i < PB; i++) {
        v[i] = g_bhist[tid * PB + i][e];
        s += v[i];
        ps += g_bprob[tid * PB + i][e];
    }
    __shared__ int sh[256];
    __shared__ float sp[256];
    sh[tid] = s; sp[tid] = ps;
    __syncthreads();
    for (int o = 1; o < 256; o <<= 1) {
        int q = (tid >= o) ? sh[tid - o] : 0;
        __syncthreads(); sh[tid] += q; __syncthreads();
    }
    int off = sh[tid] - s;
#pragma unroll
    for (int i = 0; i < PB; i++) { g_boff[tid * PB + i][e] = off; off += v[i]; }
    for (int o = 128; o > 0; o >>= 1) {
        if (tid < o) sp[tid] += sp[tid + o];
        __syncthreads();
    }
    if (tid == 0) { g_count[e] = sh[255]; g_probsum[e] = sp[0]; }
    __syncthreads();
    int c = sh[255]; if (c > CAP) c = CAP;
    int r1 = (c + 127) & ~127; if (r1 > CAP) r1 = CAP;
    for (int r = c; r < r1; r++) {
        size_t b = ((size_t)e * CAP + r) * D_DIM + tid * 4;
        *(float2*)(g_disp + b) = make_float2(0.f, 0.f);
    }
    for (int r = c + tid; r < r1; r += 256) g_inv[e * CAP + r] = -1;
}

// wsplit: in [E,R,C] fp32 -> out [E,Cpad,R] fp16 hi/lo (16B stores)
__device__ __forceinline__ void wsplit_body(
    const float* __restrict__ in, fp16* __restrict__ ohi, fp16* __restrict__ olo,
    int R, int C, int Cpad, int bx, int by, int bz, int tid)
{
    __shared__ float s[64][33];
    const float* ip = in + (size_t)bz * R * C;
    size_t ob = (size_t)bz * Cpad * R;
    int c0 = bx * 32, r0 = by * 64;
    int tx = tid & 31, ty = tid >> 5;
#pragma unroll
    for (int k = 0; k < 8; k++) {
        int r = r0 + ty + 8 * k, c = c0 + tx;
        s[ty + 8 * k][tx] = (c < C) ? ip[(size_t)r * C + c] : 0.f;
    }
    __syncthreads();
    int cl = tid >> 3, rg = (tid & 7) * 8;
    int n = c0 + cl;
    uint32_t h[4], l[4];
#pragma unroll
    for (int q = 0; q < 4; q++)
        split2u(s[rg + 2*q][cl], s[rg + 2*q + 1][cl], h[q], l[q]);
    size_t o = ob + (size_t)n * R + r0 + rg;
    *(uint4*)(ohi + o) = make_uint4(h[0], h[1], h[2], h[3]);
    *(uint4*)(olo + o) = make_uint4(l[0], l[1], l[2], l[3]);
}

__global__ void k_ws1(const float* __restrict__ W1) {
    wsplit_body(W1, g_w1t_hi, g_w1t_lo, D_DIM, H_DIM, H_DIM,
                blockIdx.x, blockIdx.y, blockIdx.z, threadIdx.x);
}
__global__ void k_ws2(const float* __restrict__ W2) {
    wsplit_body(W2, g_w2t_hi, g_w2t_lo, H_DIM, D_DIM, D_DIM,
                blockIdx.x, blockIdx.y, blockIdx.z, threadIdx.x);
}
__global__ void k_wsl(const float* __restrict__ Wl) {
    wsplit_body(Wl, g_wlt_hi, g_wlt_lo, D_DIM, NC_DIM, 1024,
                blockIdx.x, blockIdx.y, 0, threadIdx.x);
}

// dispatch (fp16 hi only) + tail loss block
__global__ void k_dispatch(const float* __restrict__ x, float* out, int out_size) {
    int b = blockIdx.x, tid = threadIdx.x;
    if (b >= N_TOK) {
        if (tid == 0 && out_size > N_TOK * NC_DIM) {
            float s = 0.f;
            for (int e = 0; e < E_NUM; e++)
                s += ((float)g_count[e] / (float)N_TOK) * (g_probsum[e] / (float)N_TOK);
            out[(size_t)N_TOK * NC_DIM] = s * (float)E_NUM;
        }
        return;
    }
    int t = b;
    int e = g_idx[t];
    int pos = g_boff[t >> 3][e] + g_lrank[t];
    if (pos < CAP) {
        if (tid == 0) g_inv[e * CAP + pos] = t;
        float4 v = ((const float4*)(x + (size_t)t * D_DIM))[tid];
        size_t o = ((size_t)e * CAP + pos) * D_DIM + tid * 4;
        *(uint2*)(g_disp + o) = make_uint2(pack2(v.x, v.y), pack2(v.z, v.w));
    } else {
        size_t o = (size_t)t * D_DIM + tid * 4;
        *(float2*)(g_y + o) = make_float2(0.f, 0.f);
    }
}

// ------ fp16 2-term GEMM: C = Ahi*(Bhi+Blo)^T, CTA 128xNT, BK=64, 2-stage --
// MODE 0: FFN1 -> h fp16 (bias+gelu)
// MODE 1: FFN2 -> y fp16 at token rows via g_inv ((acc+bias)*gate)
// MODE 2: classifier -> f32 out, col < colmax
#define OFF_B1 16384

__device__ __forceinline__ float gelu_fast(float v) {
    float u = 0.7978845608028654f * (v + 0.044715f * v * v * v);
    float t;
    asm("tanh.approx.f32 %0, %1;" : "=f"(t) : "f"(u));
    return 0.5f * v * (1.f + t);
}
__device__ __forceinline__ uint32_t swz(int row, int c) {
    return (uint32_t)(row * 128 + ((c ^ (row & 7)) << 4));
}

template <int MODE, int WI>
__global__ void __launch_bounds__(256, 1) k_mgemm(
    const fp16* __restrict__ A, size_t sAe,
    const fp16* __restrict__ Bhi, const fp16* __restrict__ Blo, size_t sBe,
    const float* __restrict__ bias, int sBiasE,
    void* __restrict__ out0, size_t sCe,
    int K, int ldc, int colmax)
{
    constexpr int NT = WI * 64;
    constexpr int STGB = OFF_B1 + 2 * NT * 128;

    int e = blockIdx.z;
    int m0 = blockIdx.y * 128, n0 = blockIdx.x * NT;
    if (MODE < 2) {
        int c = g_count[e]; if (c > CAP) c = CAP;
        if (m0 >= c) return;
    }
    A += (size_t)e * sAe;
    Bhi += (size_t)e * sBe; Blo += (size_t)e * sBe;
    bias += (size_t)e * sBiasE;

    extern __shared__ char smem_raw[];
    uint32_t base = (smem_u32(smem_raw) + 127) & ~127u;

    int tid = threadIdx.x, lane = tid & 31, wid = tid >> 5;
    int wm, wn;
    if (WI == 4) { wm = (wid >> 2) * 64; wn = (wid & 3) * 64; }
    else         { wm = (wid >> 1) * 32; wn = (wid & 1) * 64; }

    float acc[WI][8][4];
#pragma unroll
    for (int i = 0; i < WI; i++)
#pragma unroll
        for (int j = 0; j < 8; j++)
#pragma unroll
            for (int q = 0; q < 4; q++) acc[i][j][q] = 0.f;

    int nch = K >> 6;

    auto load_a = [&](int s, int c) {
        if (c >= nch) return;
        uint32_t stg = base + s * STGB;
        int k0 = c << 6;
#pragma unroll
        for (int it = 0; it < 4; it++) {
            int i = tid + it * 256;
            int row = i >> 3, cc = i & 7;
            size_t gi = (size_t)(m0 + row) * K + k0 + cc * 8;
            cpa(stg + swz(row, cc), A + gi);
        }
    };
    auto load_bh = [&](int s, int c) {
        if (c >= nch) return;
        uint32_t stg = base + s * STGB;
        int k0 = c << 6;
#pragma unroll
        for (int it = 0; it < NT / 32; it++) {
            int i = tid + it * 256;
            int row = i >> 3, cc = i & 7;
            size_t gi = (size_t)(n0 + row) * K + k0 + cc * 8;
            cpa(stg + OFF_B1 + swz(row, cc), Bhi + gi);
        }
    };
    auto load_bl = [&](int s, int c) {
        if (c >= nch) return;
        uint32_t stg = base + s * STGB;
        int k0 = c << 6;
#pragma unroll
        for (int it = 0; it < NT / 32; it++) {
            int i = tid + it * 256;
            int row = i >> 3, cc = i & 7;
            size_t gi = (size_t)(n0 + row) * K + k0 + cc * 8;
            cpa(stg + OFF_B1 + NT * 128 + swz(row, cc), Blo + gi);
        }
    };

    auto compute_ks = [&](int ks, uint32_t stg) {
        uint32_t ah[WI][4];
        int ar = wm + (lane & 15);
        int ac = ks * 2 + (lane >> 4);
#pragma unroll
        for (int i = 0; i < WI; i++)
            ldsm4(ah[i], stg + swz(ar + i * 16, ac));
        int jj = (lane >> 4);
        int brr = wn + (lane & 7);
        int bcc = ks * 2 + ((lane >> 3) & 1);
#pragma unroll
        for (int j2 = 0; j2 < 4; j2++) {
            uint32_t bh[4], bl[4];
            uint32_t adr = stg + OFF_B1 + swz(brr + (j2 * 2 + jj) * 8, bcc);
            ldsm4(bh, adr);
            ldsm4(bl, adr + NT * 128);
            int ja = j2 * 2, jb = ja + 1;
#pragma unroll
            for (int i = 0; i < WI; i++) mma_f16(acc[i][ja], ah[i], bh + 0);
#pragma unroll
            for (int i = 0; i < WI; i++) mma_f16(acc[i][jb], ah[i], bh + 2);
#pragma unroll
            for (int i = 0; i < WI; i++) mma_f16(acc[i][ja], ah[i], bl + 0);
#pragma unroll
            for (int i = 0; i < WI; i++) mma_f16(acc[i][jb], ah[i], bl + 2);
        }
    };

    load_a(0, 0); load_bh(0, 0); load_bl(0, 0); cpa_commit();

    for (int c = 0; c < nch; c++) {
        int s = c & 1;
        uint32_t stg = base + s * STGB;
        cpa_wait<0>();
        __syncthreads();
        compute_ks(0, stg);
        load_a(s ^ 1, c + 1);
        load_bh(s ^ 1, c + 1);
        compute_ks(1, stg);
        load_bl(s ^ 1, c + 1);
        cpa_commit();
        compute_ks(2, stg);
        compute_ks(3, stg);
    }

    int rb = m0 + wm, cb = n0 + wn;
#pragma unroll
    for (int i = 0; i < WI; i++)
#pragma unroll
        for (int j = 0; j < 8; j++) {
            int r0 = rb + i * 16 + (lane >> 2);
            int c0 = cb + j * 8 + (lane & 3) * 2;
            float bx = bias[c0], by = bias[c0 + 1];
#pragma unroll
            for (int h = 0; h < 2; h++) {
                int row = r0 + h * 8;
                float v0 = acc[i][j][h * 2 + 0] + bx;
                float v1 = acc[i][j][h * 2 + 1] + by;
                if (MODE == 0) {
                    size_t o = (size_t)e * sCe + (size_t)row * ldc + c0;
                    v0 = gelu_fast(v0); v1 = gelu_fast(v1);
                    *(uint32_t*)((fp16*)out0 + o) = pack2(v0, v1);
                } else if (MODE == 1) {
                    int t = g_inv[e * CAP + row];
                    if (t >= 0) {
                        float g = g_gate[t];
                        size_t o = (size_t)t * ldc + c0;
                        *(uint32_t*)((fp16*)out0 + o) = pack2(v0 * g, v1 * g);
                    }
                } else {
                    size_t oo = (size_t)row * ldc + c0;
                    if (c0 < colmax)     ((float*)out0)[oo] = v0;
                    if (c0 + 1 < colmax) ((float*)out0)[oo + 1] = v1;
                }
            }
        }
}

// ---------------- launch ----------------
extern "C" void kernel_launch(void* const* d_in, const int* in_sizes, int n_in,
                              void* d_out, int out_size) {
    const float* x  = (const float*)d_in[0];
    const float* Wg = (const float*)d_in[1];
    const float* W1 = (const float*)d_in[2];
    const float* b1 = (const float*)d_in[3];
    const float* W2 = (const float*)d_in[4];
    const float* b2 = (const float*)d_in[5];
    const float* Wl = (const float*)d_in[6];
    const float* bl = (const float*)d_in[7];
    float* out = (float*)d_out;

    const int GEMM_SMEM4 = 2 * (16384 + 2 * 256 * 128) + 128;  // 163968
    const int GEMM_SMEM2 = 2 * (16384 + 2 * 128 * 128) + 128;  // 98432

    static cudaStream_t sB = nullptr;
    static cudaEvent_t evFork, evW1, evW2, evWl;
    static int init_done = 0;
    if (!init_done) {
        cudaFuncSetAttribute((const void*)k_mgemm<0,4>, cudaFuncAttributeMaxDynamicSharedMemorySize, GEMM_SMEM4);
        cudaFuncSetAttribute((const void*)k_mgemm<1,4>, cudaFuncAttributeMaxDynamicSharedMemorySize, GEMM_SMEM4);
        cudaFuncSetAttribute((const void*)k_mgemm<2,2>, cudaFuncAttributeMaxDynamicSharedMemorySize, GEMM_SMEM2);
        cudaStreamCreateWithFlags(&sB, cudaStreamNonBlocking);
        cudaEventCreateWithFlags(&evFork, cudaEventDisableTiming);
        cudaEventCreateWithFlags(&evW1, cudaEventDisableTiming);
        cudaEventCreateWithFlags(&evW2, cudaEventDisableTiming);
        cudaEventCreateWithFlags(&evWl, cudaEventDisableTiming);
        init_done = 1;
    }

    fp16 *w1h, *w1l, *w2h, *w2l, *wlh, *wll, *dsp, *hb, *yb;
    cudaGetSymbolAddress((void**)&w1h, g_w1t_hi); cudaGetSymbolAddress((void**)&w1l, g_w1t_lo);
    cudaGetSymbolAddress((void**)&w2h, g_w2t_hi); cudaGetSymbolAddress((void**)&w2l, g_w2t_lo);
    cudaGetSymbolAddress((void**)&wlh, g_wlt_hi); cudaGetSymbolAddress((void**)&wll, g_wlt_lo);
    cudaGetSymbolAddress((void**)&dsp, g_disp);
    cudaGetSymbolAddress((void**)&hb, g_h);
    cudaGetSymbolAddress((void**)&yb, g_y);

    // fork stream B for weight splits (independent of routing)
    cudaEventRecord(evFork, 0);
    cudaStreamWaitEvent(sB, evFork, 0);
    k_ws1<<<dim3(H_DIM/32, D_DIM/64, E_NUM), 256, 0, sB>>>(W1);
    cudaEventRecord(evW1, sB);
    k_ws2<<<dim3(D_DIM/32, H_DIM/64, E_NUM), 256, 0, sB>>>(W2);
    cudaEventRecord(evW2, sB);
    k_wsl<<<dim3(1024/32, D_DIM/64, 1), 256, 0, sB>>>(Wl);
    cudaEventRecord(evWl, sB);

    // stream 0: routing chain
    k_wgt<<<64, 256>>>(Wg);
    k_gate<<<NB_GATE, 256>>>(x);
    k_scan<<<E_NUM, 256>>>();
    k_dispatch<<<N_TOK + 1, 256>>>(x, out, out_size);

    // FFN1: [CAP,1024] x (W1hi+W1lo)^T -> h fp16 (bias+gelu)
    cudaStreamWaitEvent(0, evW1, 0);
    k_mgemm<0,4><<<dim3(H_DIM/256, CAP/128, E_NUM), 256, GEMM_SMEM4>>>(
        dsp, (size_t)CAP*D_DIM, w1h, w1l, (size_t)H_DIM*D_DIM,
        b1, H_DIM, hb, (size_t)CAP*H_DIM, D_DIM, H_DIM, H_DIM);

    // FFN2 -> y fp16 at token rows (fused combine)
    cudaStreamWaitEvent(0, evW2, 0);
    k_mgemm<1,4><<<dim3(D_DIM/256, CAP/128, E_NUM), 256, GEMM_SMEM4>>>(
        hb, (size_t)CAP*H_DIM, w2h, w2l, (size_t)D_DIM*H_DIM,
        b2, D_DIM, yb, 0, H_DIM, D_DIM, D_DIM);

    // classifier: [16384,1024] x (Wlhi+Wllo)^T -> out [16384,1000] f32
    cudaStreamWaitEvent(0, evWl, 0);
    k_mgemm<2,2><<<dim3(1024/128, N_TOK/128, 1), 256, GEMM_SMEM2>>>(
        yb, 0, wlh, wll, 0,
        bl, 0, out, 0, D_DIM, NC_DIM, NC_DIM);
}

// round 17
// speedup vs baseline: 2.2197x; 1.5322x over previous
#include <cuda_runtime.h>
#include <cuda_fp16.h>
#include <math.h>
#include <stdint.h>

#define N_TOK 16384
#define D_DIM 1024
#define E_NUM 16
#define H_DIM 4096
#define NC_DIM 1000
#define CAP 2048
#define NB_GATE (N_TOK/8)

typedef __half fp16;

// ---------------- device scratch ----------------
__device__ __align__(16) fp16 g_disp[(size_t)E_NUM*CAP*D_DIM];
__device__ __align__(16) fp16 g_h[(size_t)E_NUM*CAP*H_DIM];
__device__ __align__(16) fp16 g_y[(size_t)N_TOK*D_DIM];
__device__ __align__(16) fp16 g_w1t[(size_t)E_NUM*H_DIM*D_DIM];
__device__ __align__(16) fp16 g_w2t[(size_t)E_NUM*D_DIM*H_DIM];
__device__ __align__(16) fp16 g_wlt[(size_t)1024*D_DIM];
__device__ __align__(16) float g_wgt[16*1024];       // Wg transposed [e][d]
__device__ int   g_idx[N_TOK];
__device__ float g_gate[N_TOK];
__device__ int   g_lrank[N_TOK];
__device__ int   g_bhist[NB_GATE][E_NUM];
__device__ float g_bprob[NB_GATE][E_NUM];
__device__ int   g_boff[NB_GATE][E_NUM];
__device__ int   g_count[E_NUM];
__device__ float g_probsum[E_NUM];
__device__ int   g_inv[E_NUM*CAP];

// ---------------- PTX helpers ----------------
__device__ __forceinline__ uint32_t smem_u32(const void* p) {
    return (uint32_t)__cvta_generic_to_shared(p);
}
__device__ __forceinline__ void cpa(uint32_t dst, const void* src) {
    asm volatile("cp.async.cg.shared.global [%0], [%1], 16;" :: "r"(dst), "l"(src) : "memory");
}
__device__ __forceinline__ void cpa_commit() { asm volatile("cp.async.commit_group;" ::: "memory"); }
template<int N> __device__ __forceinline__ void cpa_wait() {
    asm volatile("cp.async.wait_group %0;" :: "n"(N) : "memory");
}
__device__ __forceinline__ void ldsm4(uint32_t* r, uint32_t a) {
    asm volatile("ldmatrix.sync.aligned.m8n8.x4.shared.b16 {%0,%1,%2,%3}, [%4];"
                 : "=r"(r[0]), "=r"(r[1]), "=r"(r[2]), "=r"(r[3]) : "r"(a));
}
__device__ __forceinline__ void mma_f16(float* d, const uint32_t* a, const uint32_t* b) {
    asm volatile(
        "mma.sync.aligned.m16n8k16.row.col.f32.f16.f16.f32 "
        "{%0,%1,%2,%3}, {%4,%5,%6,%7}, {%8,%9}, {%0,%1,%2,%3};"
        : "+f"(d[0]), "+f"(d[1]), "+f"(d[2]), "+f"(d[3])
        : "r"(a[0]), "r"(a[1]), "r"(a[2]), "r"(a[3]), "r"(b[0]), "r"(b[1]));
}

__device__ __forceinline__ uint32_t pack2(float a, float b) {
    half2 h = __float22half2_rn(make_float2(a, b));
    return *(uint32_t*)&h;
}

// ---------------- Wg transpose ----------------
__global__ void k_wgt(const float* __restrict__ Wg) {
    int i = blockIdx.x * 256 + threadIdx.x;
    int d = i >> 4, e = i & 15;
    g_wgt[e * 1024 + d] = Wg[i];
}

// ---------------- gating: coalesced float4 reads of WgT ----------------
__global__ void k_gate(const float* __restrict__ x) {
    int warp = threadIdx.x >> 5, lane = threadIdx.x & 31;
    int t = blockIdx.x * 8 + warp;
    __shared__ float s_prob[E_NUM];
    __shared__ int s_idx[8];
    if (threadIdx.x < E_NUM) s_prob[threadIdx.x] = 0.f;
    __syncthreads();
    float acc[E_NUM];
#pragma unroll
    for (int e = 0; e < E_NUM; e++) acc[e] = 0.f;
    const float4* xr = (const float4*)(x + (size_t)t * D_DIM);
    const float4* wt = (const float4*)g_wgt;
#pragma unroll
    for (int j = 0; j < 8; j++) {
        int i = lane + 32 * j;
        float4 xv = xr[i];
#pragma unroll
        for (int e = 0; e < E_NUM; e++) {
            float4 w = __ldg(wt + (size_t)e * 256 + i);
            acc[e] = fmaf(xv.x, w.x, fmaf(xv.y, w.y,
                     fmaf(xv.z, w.z, fmaf(xv.w, w.w, acc[e]))));
        }
    }
#pragma unroll
    for (int e = 0; e < E_NUM; e++)
#pragma unroll
        for (int o = 16; o > 0; o >>= 1) acc[e] += __shfl_xor_sync(0xffffffffu, acc[e], o);
    if (lane == 0) {
        float m = acc[0]; int ai = 0;
#pragma unroll
        for (int e = 1; e < E_NUM; e++) if (acc[e] > m) { m = acc[e]; ai = e; }
        float p[E_NUM]; float s = 0.f;
#pragma unroll
        for (int e = 0; e < E_NUM; e++) { p[e] = expf(acc[e] - m); s += p[e]; }
        float inv = 1.f / s;
#pragma unroll
        for (int e = 0; e < E_NUM; e++) atomicAdd(&s_prob[e], p[e] * inv);
        g_idx[t] = ai; g_gate[t] = p[ai] * inv; s_idx[warp] = ai;
    }
    __syncthreads();
    if (threadIdx.x == 0) {
        int cnt[E_NUM];
#pragma unroll
        for (int e = 0; e < E_NUM; e++) cnt[e] = 0;
#pragma unroll
        for (int w = 0; w < 8; w++) {
            int e = s_idx[w];
            g_lrank[blockIdx.x * 8 + w] = cnt[e];
            cnt[e]++;
        }
#pragma unroll
        for (int e = 0; e < E_NUM; e++) g_bhist[blockIdx.x][e] = cnt[e];
    }
    if (threadIdx.x < E_NUM) g_bprob[blockIdx.x][threadIdx.x] = s_prob[threadIdx.x];
}

// ---------------- scan + probsum reduce + pad ----------------
__global__ void k_scan() {
    const int PB = NB_GATE / 256;
    int e = blockIdx.x, tid = threadIdx.x;
    int v[PB]; int s = 0;
    float ps = 0.f;
#pragma unroll
    for (int i = 0; i < PB; i++) {
        v[i] = g_bhist[tid * PB + i][e];
        s += v[i];
        ps += g_bprob[tid * PB + i][e];
    }
    __shared__ int sh[256];
    __shared__ float sp[256];
    sh[tid] = s; sp[tid] = ps;
    __syncthreads();
    for (int o = 1; o < 256; o <<= 1) {
        int q = (tid >= o) ? sh[tid - o] : 0;
        __syncthreads(); sh[tid] += q; __syncthreads();
    }
    int off = sh[tid] - s;
#pragma unroll
    for (int i = 0; i < PB; i++) { g_boff[tid * PB + i][e] = off; off += v[i]; }
    for (int o = 128; o > 0; o >>= 1) {
        if (tid < o) sp[tid] += sp[tid + o];
        __syncthreads();
    }
    if (tid == 0) { g_count[e] = sh[255]; g_probsum[e] = sp[0]; }
    __syncthreads();
    int c = sh[255]; if (c > CAP) c = CAP;
    int r1 = (c + 127) & ~127; if (r1 > CAP) r1 = CAP;
    for (int r = c; r < r1; r++) {
        size_t b = ((size_t)e * CAP + r) * D_DIM + tid * 4;
        *(float2*)(g_disp + b) = make_float2(0.f, 0.f);
    }
    for (int r = c + tid; r < r1; r += 256) g_inv[e * CAP + r] = -1;
}

// wconv: in [E,R,C] fp32 -> out [E,Cpad,R] fp16 (16B stores)
__device__ __forceinline__ void wconv_body(
    const float* __restrict__ in, fp16* __restrict__ ot,
    int R, int C, int Cpad, int bx, int by, int bz, int tid)
{
    __shared__ float s[64][33];
    const float* ip = in + (size_t)bz * R * C;
    size_t ob = (size_t)bz * Cpad * R;
    int c0 = bx * 32, r0 = by * 64;
    int tx = tid & 31, ty = tid >> 5;
#pragma unroll
    for (int k = 0; k < 8; k++) {
        int r = r0 + ty + 8 * k, c = c0 + tx;
        s[ty + 8 * k][tx] = (c < C) ? ip[(size_t)r * C + c] : 0.f;
    }
    __syncthreads();
    int cl = tid >> 3, rg = (tid & 7) * 8;
    int n = c0 + cl;
    uint32_t h[4];
#pragma unroll
    for (int q = 0; q < 4; q++)
        h[q] = pack2(s[rg + 2*q][cl], s[rg + 2*q + 1][cl]);
    size_t o = ob + (size_t)n * R + r0 + rg;
    *(uint4*)(ot + o) = make_uint4(h[0], h[1], h[2], h[3]);
}

__global__ void k_ws1(const float* __restrict__ W1) {
    wconv_body(W1, g_w1t, D_DIM, H_DIM, H_DIM,
               blockIdx.x, blockIdx.y, blockIdx.z, threadIdx.x);
}
__global__ void k_ws2(const float* __restrict__ W2) {
    wconv_body(W2, g_w2t, H_DIM, D_DIM, D_DIM,
               blockIdx.x, blockIdx.y, blockIdx.z, threadIdx.x);
}
__global__ void k_wsl(const float* __restrict__ Wl) {
    wconv_body(Wl, g_wlt, D_DIM, NC_DIM, 1024,
               blockIdx.x, blockIdx.y, 0, threadIdx.x);
}

// dispatch (fp16) + tail loss block
__global__ void k_dispatch(const float* __restrict__ x, float* out, int out_size) {
    int b = blockIdx.x, tid = threadIdx.x;
    if (b >= N_TOK) {
        if (tid == 0 && out_size > N_TOK * NC_DIM) {
            float s = 0.f;
            for (int e = 0; e < E_NUM; e++)
                s += ((float)g_count[e] / (float)N_TOK) * (g_probsum[e] / (float)N_TOK);
            out[(size_t)N_TOK * NC_DIM] = s * (float)E_NUM;
        }
        return;
    }
    int t = b;
    int e = g_idx[t];
    int pos = g_boff[t >> 3][e] + g_lrank[t];
    if (pos < CAP) {
        if (tid == 0) g_inv[e * CAP + pos] = t;
        float4 v = ((const float4*)(x + (size_t)t * D_DIM))[tid];
        size_t o = ((size_t)e * CAP + pos) * D_DIM + tid * 4;
        *(uint2*)(g_disp + o) = make_uint2(pack2(v.x, v.y), pack2(v.z, v.w));
    } else {
        size_t o = (size_t)t * D_DIM + tid * 4;
        *(float2*)(g_y + o) = make_float2(0.f, 0.f);
    }
}

// ------ pure fp16 GEMM: C = A*B^T (fp32 accum), CTA 128xNT, BK=64, 2-stage -
// MODE 0: FFN1 -> h fp16 (bias+gelu)
// MODE 1: FFN2 -> y fp16 at token rows via g_inv ((acc+bias)*gate)
// MODE 2: classifier -> f32 out, col < colmax
#define OFF_B1 16384

__device__ __forceinline__ float gelu_fast(float v) {
    float u = 0.7978845608028654f * (v + 0.044715f * v * v * v);
    float t;
    asm("tanh.approx.f32 %0, %1;" : "=f"(t) : "f"(u));
    return 0.5f * v * (1.f + t);
}
__device__ __forceinline__ uint32_t swz(int row, int c) {
    return (uint32_t)(row * 128 + ((c ^ (row & 7)) << 4));
}

template <int MODE, int WI>
__global__ void __launch_bounds__(256, 1) k_mgemm(
    const fp16* __restrict__ A, size_t sAe,
    const fp16* __restrict__ B, size_t sBe,
    const float* __restrict__ bias, int sBiasE,
    void* __restrict__ out0, size_t sCe,
    int K, int ldc, int colmax)
{
    constexpr int NT = WI * 64;
    constexpr int STGB = OFF_B1 + NT * 128;

    int e = blockIdx.z;
    int m0 = blockIdx.y * 128, n0 = blockIdx.x * NT;
    if (MODE < 2) {
        int c = g_count[e]; if (c > CAP) c = CAP;
        if (m0 >= c) return;
    }
    A += (size_t)e * sAe;
    B += (size_t)e * sBe;
    bias += (size_t)e * sBiasE;

    extern __shared__ char smem_raw[];
    uint32_t base = (smem_u32(smem_raw) + 127) & ~127u;

    int tid = threadIdx.x, lane = tid & 31, wid = tid >> 5;
    int wm, wn;
    if (WI == 4) { wm = (wid >> 2) * 64; wn = (wid & 3) * 64; }
    else         { wm = (wid >> 1) * 32; wn = (wid & 1) * 64; }

    float acc[WI][8][4];
#pragma unroll
    for (int i = 0; i < WI; i++)
#pragma unroll
        for (int j = 0; j < 8; j++)
#pragma unroll
            for (int q = 0; q < 4; q++) acc[i][j][q] = 0.f;

    int nch = K >> 6;

    auto load_a = [&](int s, int c) {
        if (c >= nch) return;
        uint32_t stg = base + s * STGB;
        int k0 = c << 6;
#pragma unroll
        for (int it = 0; it < 4; it++) {
            int i = tid + it * 256;
            int row = i >> 3, cc = i & 7;
            size_t gi = (size_t)(m0 + row) * K + k0 + cc * 8;
            cpa(stg + swz(row, cc), A + gi);
        }
    };
    auto load_b = [&](int s, int c) {
        if (c >= nch) return;
        uint32_t stg = base + s * STGB;
        int k0 = c << 6;
#pragma unroll
        for (int it = 0; it < NT / 32; it++) {
            int i = tid + it * 256;
            int row = i >> 3, cc = i & 7;
            size_t gi = (size_t)(n0 + row) * K + k0 + cc * 8;
            cpa(stg + OFF_B1 + swz(row, cc), B + gi);
        }
    };

    auto compute_ks = [&](int ks, uint32_t stg) {
        uint32_t ah[WI][4];
        int ar = wm + (lane & 15);
        int ac = ks * 2 + (lane >> 4);
#pragma unroll
        for (int i = 0; i < WI; i++)
            ldsm4(ah[i], stg + swz(ar + i * 16, ac));
        int jj = (lane >> 4);
        int brr = wn + (lane & 7);
        int bcc = ks * 2 + ((lane >> 3) & 1);
#pragma unroll
        for (int j2 = 0; j2 < 4; j2++) {
            uint32_t bh[4];
            ldsm4(bh, stg + OFF_B1 + swz(brr + (j2 * 2 + jj) * 8, bcc));
            int ja = j2 * 2, jb = ja + 1;
#pragma unroll
            for (int i = 0; i < WI; i++) mma_f16(acc[i][ja], ah[i], bh + 0);
#pragma unroll
            for (int i = 0; i < WI; i++) mma_f16(acc[i][jb], ah[i], bh + 2);
        }
    };

    load_a(0, 0); load_b(0, 0); cpa_commit();

    for (int c = 0; c < nch; c++) {
        int s = c & 1;
        uint32_t stg = base + s * STGB;
        cpa_wait<0>();
        __syncthreads();
        compute_ks(0, stg);
        load_a(s ^ 1, c + 1);
        compute_ks(1, stg);
        load_b(s ^ 1, c + 1);
        cpa_commit();
        compute_ks(2, stg);
        compute_ks(3, stg);
    }

    int rb = m0 + wm, cb = n0 + wn;
#pragma unroll
    for (int i = 0; i < WI; i++)
#pragma unroll
        for (int j = 0; j < 8; j++) {
            int r0 = rb + i * 16 + (lane >> 2);
            int c0 = cb + j * 8 + (lane & 3) * 2;
            float bx = bias[c0], by = bias[c0 + 1];
#pragma unroll
            for (int h = 0; h < 2; h++) {
                int row = r0 + h * 8;
                float v0 = acc[i][j][h * 2 + 0] + bx;
                float v1 = acc[i][j][h * 2 + 1] + by;
                if (MODE == 0) {
                    size_t o = (size_t)e * sCe + (size_t)row * ldc + c0;
                    v0 = gelu_fast(v0); v1 = gelu_fast(v1);
                    *(uint32_t*)((fp16*)out0 + o) = pack2(v0, v1);
                } else if (MODE == 1) {
                    int t = g_inv[e * CAP + row];
                    if (t >= 0) {
                        float g = g_gate[t];
                        size_t o = (size_t)t * ldc + c0;
                        *(uint32_t*)((fp16*)out0 + o) = pack2(v0 * g, v1 * g);
                    }
                } else {
                    size_t oo = (size_t)row * ldc + c0;
                    if (c0 < colmax)     ((float*)out0)[oo] = v0;
                    if (c0 + 1 < colmax) ((float*)out0)[oo + 1] = v1;
                }
            }
        }
}

// ---------------- launch ----------------
extern "C" void kernel_launch(void* const* d_in, const int* in_sizes, int n_in,
                              void* d_out, int out_size) {
    const float* x  = (const float*)d_in[0];
    const float* Wg = (const float*)d_in[1];
    const float* W1 = (const float*)d_in[2];
    const float* b1 = (const float*)d_in[3];
    const float* W2 = (const float*)d_in[4];
    const float* b2 = (const float*)d_in[5];
    const float* Wl = (const float*)d_in[6];
    const float* bl = (const float*)d_in[7];
    float* out = (float*)d_out;

    const int GEMM_SMEM4 = 2 * (16384 + 256 * 128) + 128;  // 98432
    const int GEMM_SMEM2 = 2 * (16384 + 128 * 128) + 128;  // 65664

    static cudaStream_t sB = nullptr;
    static cudaEvent_t evFork, evW1, evW2, evWl;
    static int init_done = 0;
    if (!init_done) {
        cudaFuncSetAttribute((const void*)k_mgemm<0,4>, cudaFuncAttributeMaxDynamicSharedMemorySize, GEMM_SMEM4);
        cudaFuncSetAttribute((const void*)k_mgemm<1,4>, cudaFuncAttributeMaxDynamicSharedMemorySize, GEMM_SMEM4);
        cudaFuncSetAttribute((const void*)k_mgemm<2,2>, cudaFuncAttributeMaxDynamicSharedMemorySize, GEMM_SMEM2);
        cudaStreamCreateWithFlags(&sB, cudaStreamNonBlocking);
        cudaEventCreateWithFlags(&evFork, cudaEventDisableTiming);
        cudaEventCreateWithFlags(&evW1, cudaEventDisableTiming);
        cudaEventCreateWithFlags(&evW2, cudaEventDisableTiming);
        cudaEventCreateWithFlags(&evWl, cudaEventDisableTiming);
        init_done = 1;
    }

    fp16 *w1t, *w2t, *wlt, *dsp, *hb, *yb;
    cudaGetSymbolAddress((void**)&w1t, g_w1t);
    cudaGetSymbolAddress((void**)&w2t, g_w2t);
    cudaGetSymbolAddress((void**)&wlt, g_wlt);
    cudaGetSymbolAddress((void**)&dsp, g_disp);
    cudaGetSymbolAddress((void**)&hb, g_h);
    cudaGetSymbolAddress((void**)&yb, g_y);

    // fork stream B for weight conversion (independent of routing)
    cudaEventRecord(evFork, 0);
    cudaStreamWaitEvent(sB, evFork, 0);
    k_ws1<<<dim3(H_DIM/32, D_DIM/64, E_NUM), 256, 0, sB>>>(W1);
    cudaEventRecord(evW1, sB);
    k_ws2<<<dim3(D_DIM/32, H_DIM/64, E_NUM), 256, 0, sB>>>(W2);
    cudaEventRecord(evW2, sB);
    k_wsl<<<dim3(1024/32, D_DIM/64, 1), 256, 0, sB>>>(Wl);
    cudaEventRecord(evWl, sB);

    // stream 0: routing chain
    k_wgt<<<64, 256>>>(Wg);
    k_gate<<<NB_GATE, 256>>>(x);
    k_scan<<<E_NUM, 256>>>();
    k_dispatch<<<N_TOK + 1, 256>>>(x, out, out_size);

    // FFN1: [CAP,1024] x W1t^T -> h fp16 (bias+gelu)
    cudaStreamWaitEvent(0, evW1, 0);
    k_mgemm<0,4><<<dim3(H_DIM/256, CAP/128, E_NUM), 256, GEMM_SMEM4>>>(
        dsp, (size_t)CAP*D_DIM, w1t, (size_t)H_DIM*D_DIM,
        b1, H_DIM, hb, (size_t)CAP*H_DIM, D_DIM, H_DIM, H_DIM);

    // FFN2 -> y fp16 at token rows (fused combine)
    cudaStreamWaitEvent(0, evW2, 0);
    k_mgemm<1,4><<<dim3(D_DIM/256, CAP/128, E_NUM), 256, GEMM_SMEM4>>>(
        hb, (size_t)CAP*H_DIM, w2t, (size_t)D_DIM*H_DIM,
        b2, D_DIM, yb, 0, H_DIM, D_DIM, D_DIM);

    // classifier: [16384,1024] x Wlt^T -> out [16384,1000] f32
    cudaStreamWaitEvent(0, evWl, 0);
    k_mgemm<2,2><<<dim3(1024/128, N_TOK/128, 1), 256, GEMM_SMEM2>>>(
        yb, 0, wlt, 0,
        bl, 0, out, 0, D_DIM, NC_DIM, NC_DIM);
}